// round 1
// baseline (speedup 1.0000x reference)
#include <cuda_runtime.h>

// LIF neuron scan: for each spatial location, over T=16 steps:
//   u1 = mem*0.5 + x[t]*0.5 ; spike = (u1 > 1.0) ; mem = spike ? 0 : u1
// Output = spikes as fp32. Pure streaming, HBM-bound.

#define TSTEPS 16

__global__ void __launch_bounds__(256)
lif_scan_kernel(const float* __restrict__ x, float* __restrict__ out, int n_per_step)
{
    // Each thread owns 4 consecutive spatial locations (float4).
    long long idx = ((long long)blockIdx.x * blockDim.x + threadIdx.x) * 4;
    if (idx >= n_per_step) return;

    float4 mem = make_float4(0.f, 0.f, 0.f, 0.f);

    #pragma unroll
    for (int t = 0; t < TSTEPS; ++t) {
        long long off = (long long)t * n_per_step + idx;
        const float4 xt = *reinterpret_cast<const float4*>(x + off);

        float4 u, s;
        u.x = fmaf(mem.x, 0.5f, xt.x * 0.5f);
        u.y = fmaf(mem.y, 0.5f, xt.y * 0.5f);
        u.z = fmaf(mem.z, 0.5f, xt.z * 0.5f);
        u.w = fmaf(mem.w, 0.5f, xt.w * 0.5f);

        s.x = (u.x > 1.0f) ? 1.0f : 0.0f;
        s.y = (u.y > 1.0f) ? 1.0f : 0.0f;
        s.z = (u.z > 1.0f) ? 1.0f : 0.0f;
        s.w = (u.w > 1.0f) ? 1.0f : 0.0f;

        mem.x = (u.x > 1.0f) ? 0.0f : u.x;
        mem.y = (u.y > 1.0f) ? 0.0f : u.y;
        mem.z = (u.z > 1.0f) ? 0.0f : u.z;
        mem.w = (u.w > 1.0f) ? 0.0f : u.w;

        *reinterpret_cast<float4*>(out + off) = s;
    }
}

extern "C" void kernel_launch(void* const* d_in, const int* in_sizes, int n_in,
                              void* d_out, int out_size)
{
    const float* x = (const float*)d_in[0];
    float* out = (float*)d_out;

    int total = in_sizes[0];
    int n_per_step = total / TSTEPS;          // 4,194,304 (divisible by 4)

    int threads = 256;
    long long n_thr = (long long)n_per_step / 4;
    int blocks = (int)((n_thr + threads - 1) / threads);

    lif_scan_kernel<<<blocks, threads>>>(x, out, n_per_step);
}

// round 2
// speedup vs baseline: 1.0136x; 1.0136x over previous
#include <cuda_runtime.h>

// LIF neuron scan, T=16:
//   u1 = mem*0.5 + x[t]*0.5 ; spike = (u1 > 1) ; mem = spike ? 0 : u1
// HBM-bound streaming. Strategy: batch all 16 timestep loads up front
// (MLP=16, long read burst), compute the recurrence in registers, then
// emit all 16 stores as one write burst. .cs hints = evict-first (no reuse).

#define TSTEPS 16

__global__ void __launch_bounds__(256)
lif_scan_kernel(const float* __restrict__ x, float* __restrict__ out, int n_per_step)
{
    long long idx = ((long long)blockIdx.x * blockDim.x + threadIdx.x) * 4;
    if (idx >= n_per_step) return;

    const float4* __restrict__ xp = reinterpret_cast<const float4*>(x + idx);
    float4* __restrict__ op = reinterpret_cast<float4*>(out + idx);
    const long long stride4 = n_per_step / 4;   // float4 stride between timesteps

    // Phase 1: batched read burst — 16 independent LDG.128, streaming hint.
    float4 v[TSTEPS];
    #pragma unroll
    for (int t = 0; t < TSTEPS; ++t)
        v[t] = __ldcs(xp + (long long)t * stride4);

    // Phase 2: recurrence in registers (in-place: v[t] becomes the spike).
    float4 mem = make_float4(0.f, 0.f, 0.f, 0.f);
    #pragma unroll
    for (int t = 0; t < TSTEPS; ++t) {
        float ux = fmaf(mem.x, 0.5f, v[t].x * 0.5f);
        float uy = fmaf(mem.y, 0.5f, v[t].y * 0.5f);
        float uz = fmaf(mem.z, 0.5f, v[t].z * 0.5f);
        float uw = fmaf(mem.w, 0.5f, v[t].w * 0.5f);

        v[t].x = (ux > 1.0f) ? 1.0f : 0.0f;
        v[t].y = (uy > 1.0f) ? 1.0f : 0.0f;
        v[t].z = (uz > 1.0f) ? 1.0f : 0.0f;
        v[t].w = (uw > 1.0f) ? 1.0f : 0.0f;

        mem.x = (ux > 1.0f) ? 0.0f : ux;
        mem.y = (uy > 1.0f) ? 0.0f : uy;
        mem.z = (uz > 1.0f) ? 0.0f : uz;
        mem.w = (uw > 1.0f) ? 0.0f : uw;
    }

    // Phase 3: batched write burst — 16 STG.128, streaming hint.
    #pragma unroll
    for (int t = 0; t < TSTEPS; ++t)
        __stcs(op + (long long)t * stride4, v[t]);
}

extern "C" void kernel_launch(void* const* d_in, const int* in_sizes, int n_in,
                              void* d_out, int out_size)
{
    const float* x = (const float*)d_in[0];
    float* out = (float*)d_out;

    int total = in_sizes[0];
    int n_per_step = total / TSTEPS;          // 4,194,304

    int threads = 256;
    long long n_thr = (long long)n_per_step / 4;
    int blocks = (int)((n_thr + threads - 1) / threads);

    lif_scan_kernel<<<blocks, threads>>>(x, out, n_per_step);
}